// round 10
// baseline (speedup 1.0000x reference)
#include <cuda_runtime.h>
#include <cuda_bf16.h>

#define BLOCK 1024
#define GRID  304            // 152 SMs * 2 CTAs
#define MAX_MOL 4096
#define PACK_WORDS_CAP (1 << 20)     // u32 words; 16 atoms/word -> up to 16M atoms

__device__ unsigned g_packed[PACK_WORDS_CAP];

// ---------------------------------------------------------------------------
// Prep: pack species (0..3) into 2-bit entries (16/word) AND init output.
// ---------------------------------------------------------------------------
__global__ void prep_kernel(const int* __restrict__ sp,
                            const float* __restrict__ energies,
                            float* __restrict__ out,
                            int n_species, int n_mol, int with_species) {
    int i = blockIdx.x * blockDim.x + threadIdx.x;
    int n_words = (n_species + 15) >> 4;

    if (i < n_words) {
        int base = i * 16;
        unsigned v = 0;
        if (base + 16 <= n_species) {
            const int4* p = (const int4*)(sp + base);
#pragma unroll
            for (int q = 0; q < 4; q++) {
                int4 s = p[q];
                v |= ((unsigned)s.x & 3u) << (2 * (q * 4 + 0));
                v |= ((unsigned)s.y & 3u) << (2 * (q * 4 + 1));
                v |= ((unsigned)s.z & 3u) << (2 * (q * 4 + 2));
                v |= ((unsigned)s.w & 3u) << (2 * (q * 4 + 3));
            }
        } else {
            for (int k = 0; k < 16 && base + k < n_species; k++)
                v |= ((unsigned)sp[base + k] & 3u) << (2 * k);
        }
        g_packed[i] = v;
    }

    if (with_species) {
        if (i < n_species) out[i] = (float)sp[i];
        if (i < n_mol)     out[n_species + i] = energies[i];
    } else {
        if (i < n_mol)     out[i] = energies[i];
    }
}

// ---------------------------------------------------------------------------
// Main kernel.
// Dynamic smem: [ hist: MAX_MOL f32 ][ pre_rep: 512 f32 ][ df_rep: 512 f32 ]
//               [ species tbl: n_words u32 ]
// pre_rep[t*32+lane] = ep[t] * e          (absorbs the +1 in the exponent)
// df_rep[t*32+lane]  = df[t] * A2B * log2(e)
// Zero-bank-conflict: every lane always reads its own bank.
// srb = pre_e[t] * 2^( df2[t]*dd - log2e/(1-x2) ),  x2 = (dd/5.2)^2
// ---------------------------------------------------------------------------
template <bool POW2, bool SMEM_TBL>
__global__ __launch_bounds__(BLOCK, 2) void srb_kernel(
    const int*   __restrict__ idx12,
    const float* __restrict__ dist,
    const float* __restrict__ ep,
    const float* __restrict__ df,
    float*       __restrict__ out_energy,
    int n_pairs, int shift, int n_atoms, int n_mol, int n_words)
{
    extern __shared__ unsigned char smem_raw[];
    float*    hist    = (float*)smem_raw;
    float*    pre_rep = (float*)(smem_raw + MAX_MOL * sizeof(float));
    float*    df_rep  = pre_rep + 512;
    unsigned* tbl     = (unsigned*)(df_rep + 512);

    const float A2B    = 1.8897261258369282f;
    const float LOG2E  = 1.4426950408889634f;
    const float kEuler = 2.7182818284590452f;
    const float c1     = 1.0f / (5.2f * 5.2f);   // (dd/5.2)^2, angstrom

    for (int i = threadIdx.x; i < MAX_MOL; i += BLOCK) hist[i] = 0.0f;
    if (threadIdx.x < 512) {
        int t = threadIdx.x >> 5;
        pre_rep[threadIdx.x] = ep[t] * kEuler;
        df_rep[threadIdx.x]  = df[t] * A2B * LOG2E;
    }
    if (SMEM_TBL) {
        for (int i = threadIdx.x; i < n_words; i += BLOCK)
            tbl[i] = g_packed[i];
    }
    __syncthreads();

    const unsigned lane = threadIdx.x & 31u;

    const int nvec = n_pairs >> 2;
    const int4*   iv1 = (const int4*)idx12;
    const int4*   iv2 = (const int4*)(idx12 + n_pairs);
    const float4* dv  = (const float4*)dist;

    const int stride = GRID * BLOCK;
    for (int p = blockIdx.x * BLOCK + threadIdx.x; p < nvec; p += stride) {
        int4   a = __ldcs(&iv1[p]);
        int4   b = __ldcs(&iv2[p]);
        float4 w = __ldcs(&dv[p]);

        int   i1[4] = {a.x, a.y, a.z, a.w};
        int   i2[4] = {b.x, b.y, b.z, b.w};
        float dd[4] = {w.x, w.y, w.z, w.w};

#pragma unroll
        for (int k = 0; k < 4; k++) {
            float x2 = dd[k] * dd[k] * c1;
            if (x2 < 1.0f) {
                unsigned u1 = (unsigned)i1[k];
                unsigned u2 = (unsigned)i2[k];
                unsigned w1 = SMEM_TBL ? tbl[u1 >> 4] : __ldg(&g_packed[u1 >> 4]);
                unsigned w2 = SMEM_TBL ? tbl[u2 >> 4] : __ldg(&g_packed[u2 >> 4]);
                unsigned sa = (w1 >> ((u1 & 15u) * 2u)) & 3u;
                unsigned sb = (w2 >> ((u2 & 15u) * 2u)) & 3u;
                unsigned ti = ((sa * 4u + sb) << 5) | lane;
                float rcp2 = __fdividef(LOG2E, 1.0f - x2);
                float E2   = fmaf(df_rep[ti], dd[k], -rcp2);
                float srb  = pre_rep[ti] * exp2f(E2);
                unsigned mol = POW2 ? (u1 >> shift) : (u1 / (unsigned)n_atoms);
                atomicAdd(&hist[mol], srb);
            }
        }
    }

    // scalar tail
    if (blockIdx.x == 0) {
        for (int p = nvec * 4 + threadIdx.x; p < n_pairs; p += BLOCK) {
            unsigned u1 = (unsigned)idx12[p];
            unsigned u2 = (unsigned)idx12[p + n_pairs];
            float ddk = dist[p];
            float x2  = ddk * ddk * c1;
            if (x2 < 1.0f) {
                unsigned w1 = SMEM_TBL ? tbl[u1 >> 4] : __ldg(&g_packed[u1 >> 4]);
                unsigned w2 = SMEM_TBL ? tbl[u2 >> 4] : __ldg(&g_packed[u2 >> 4]);
                unsigned sa = (w1 >> ((u1 & 15u) * 2u)) & 3u;
                unsigned sb = (w2 >> ((u2 & 15u) * 2u)) & 3u;
                unsigned ti = ((sa * 4u + sb) << 5) | lane;
                float rcp2 = __fdividef(LOG2E, 1.0f - x2);
                float E2   = fmaf(df_rep[ti], ddk, -rcp2);
                float srb  = pre_rep[ti] * exp2f(E2);
                unsigned mol = POW2 ? (u1 >> shift) : (u1 / (unsigned)n_atoms);
                atomicAdd(&hist[mol], srb);
            }
        }
    }
    __syncthreads();

    for (int i = threadIdx.x; i < n_mol; i += BLOCK) {
        float v = hist[i];
        if (v != 0.0f) atomicAdd(&out_energy[i], v);
    }
}

// ---------------------------------------------------------------------------
extern "C" void kernel_launch(void* const* d_in, const int* in_sizes, int n_in,
                              void* d_out, int out_size) {
    const int*   species  = (const int*)  d_in[0];
    const float* energies = (const float*)d_in[1];
    const int*   idx12    = (const int*)  d_in[2];
    const float* dist     = (const float*)d_in[3];
    const float* ep       = (const float*)d_in[4];
    const float* df       = (const float*)d_in[5];

    int n_species = in_sizes[0];
    int n_mol     = in_sizes[1];
    int n_pairs   = in_sizes[3];
    int n_atoms   = n_species / n_mol;
    int n_words   = (n_species + 15) >> 4;

    int with_species = (out_size > n_mol) ? 1 : 0;
    float* out        = (float*)d_out;
    float* out_energy = with_species ? (out + n_species) : out;

    int shift = -1;
    if (n_atoms > 0 && (n_atoms & (n_atoms - 1)) == 0) {
        shift = 0;
        int v = n_atoms;
        while (v > 1) { v >>= 1; shift++; }
    }

    int prep_n = (n_species > n_mol ? n_species : n_mol);
    prep_kernel<<<(prep_n + 255) / 256, 256>>>(species, energies, out,
                                               n_species, n_mol, with_species);

    size_t dyn_base = (size_t)MAX_MOL * 4 + 1024 * 4;  // hist + replicated tables
    size_t dyn_tbl  = dyn_base + (size_t)n_words * 4;
    bool use_smem_tbl = (n_mol <= MAX_MOL) && (dyn_tbl <= 96 * 1024);

    if (use_smem_tbl) {
        if (shift >= 0) {
            cudaFuncSetAttribute(srb_kernel<true, true>,
                                 cudaFuncAttributeMaxDynamicSharedMemorySize,
                                 (int)dyn_tbl);
            srb_kernel<true, true><<<GRID, BLOCK, dyn_tbl>>>(
                idx12, dist, ep, df, out_energy, n_pairs, shift, n_atoms, n_mol, n_words);
        } else {
            cudaFuncSetAttribute(srb_kernel<false, true>,
                                 cudaFuncAttributeMaxDynamicSharedMemorySize,
                                 (int)dyn_tbl);
            srb_kernel<false, true><<<GRID, BLOCK, dyn_tbl>>>(
                idx12, dist, ep, df, out_energy, n_pairs, shift, n_atoms, n_mol, n_words);
        }
    } else {
        if (shift >= 0) {
            cudaFuncSetAttribute(srb_kernel<true, false>,
                                 cudaFuncAttributeMaxDynamicSharedMemorySize,
                                 (int)dyn_base);
            srb_kernel<true, false><<<GRID, BLOCK, dyn_base>>>(
                idx12, dist, ep, df, out_energy, n_pairs, shift, n_atoms, n_mol, n_words);
        } else {
            cudaFuncSetAttribute(srb_kernel<false, false>,
                                 cudaFuncAttributeMaxDynamicSharedMemorySize,
                                 (int)dyn_base);
            srb_kernel<false, false><<<GRID, BLOCK, dyn_base>>>(
                idx12, dist, ep, df, out_energy, n_pairs, shift, n_atoms, n_mol, n_words);
        }
    }
}